// round 14
// baseline (speedup 1.0000x reference)
#include <cuda_runtime.h>
#include <cuda_fp16.h>
#include <cstdint>

// Problem constants (fixed by setup_inputs)
#define TOKENS 16384
#define DIM    1024
#define CD     16
#define CS     8192

#define N_X  (TOKENS * DIM)
#define N_W  (CD * DIM)
#define N_CB (CS * CD)

// ---- scan tiling ----
#define CHUNK_N   128
#define NCHUNK    (CS / CHUNK_N)      // 64
#define ROWB      112                 // bytes/code row: 56 halves (48 data + 8 pad)
#define SCAN_THREADS 512
#define KB        3                   // fp16 2-split products: hh,hm,mh
#define WSLICE    16
#define WSLICE_B  (WSLICE * ROWB)     // 1792 B
#define WAREA     (2 * WSLICE_B + 2 * 64)

#define OFF_Z    (16 * WAREA)
#define OFF_RES  (OFF_Z + 128 * CD * 4)
#define SCAN_SMEM (OFF_RES + 128 * 8)

// proj config (fused kernel)
#define P1_THREADS 256
#define P1_TPB     64                 // tokens per block, 4 thr/token
#define P1_DC      64                 // D chunk
#define P1_XS      68                 // padded x row stride (floats)

#define NB_PROJ  (TOKENS / P1_TPB)          // 256
#define NB_IMG   (CS * 4 / 256)             // 128
#define NB_PREP  (CS / 256)                 // 32
#define NB_FUSED (NB_PROJ + NB_IMG + NB_PREP)

__device__ __align__(16) float g_z[TOKENS * CD];
__device__ float g_hbneg[CS];
__device__ __align__(16) unsigned char g_img[CS * ROWB];

// ---------------- helpers ----------------
__device__ __forceinline__ uint32_t smem_u32(const void* p) {
    uint32_t a;
    asm("{ .reg .u64 t; cvta.to.shared.u64 t, %1; cvt.u32.u64 %0, t; }"
        : "=r"(a) : "l"(p));
    return a;
}
__device__ __forceinline__ void cpa16(uint32_t dst, const void* src) {
    asm volatile("cp.async.ca.shared.global [%0], [%1], 16;"
                 :: "r"(dst), "l"(src) : "memory");
}
__device__ __forceinline__ void cpa_commit() {
    asm volatile("cp.async.commit_group;" ::: "memory");
}
__device__ __forceinline__ void cpa_wait1() {
    asm volatile("cp.async.wait_group 1;" ::: "memory");
}
__device__ __forceinline__ void cpa_wait0() {
    asm volatile("cp.async.wait_group 0;" ::: "memory");
}
__device__ __forceinline__ unsigned int ordf(float f) {
    unsigned int u = __float_as_uint(f);
    return (u & 0x80000000u) ? ~u : (u | 0x80000000u);
}
__device__ __forceinline__ void split2(float f, unsigned short& h, unsigned short& m) {
    __half hh = __float2half_rn(f);
    float fh = __half2float(hh);
    __half mm = __float2half_rn(f - fh);
    h = *reinterpret_cast<unsigned short*>(&hh);
    m = *reinterpret_cast<unsigned short*>(&mm);
}
__device__ __forceinline__ int lvlA(int kb) { return kb >> 1; }
__device__ __forceinline__ int lvlB(int kb) { return kb & 1; }

__device__ __forceinline__ void mma16816(float* d, const uint32_t* a,
                                         uint32_t b0, uint32_t b1) {
    asm volatile(
        "mma.sync.aligned.m16n8k16.row.col.f32.f16.f16.f32 "
        "{%0,%1,%2,%3},{%4,%5,%6,%7},{%8,%9},{%0,%1,%2,%3};"
        : "+f"(d[0]), "+f"(d[1]), "+f"(d[2]), "+f"(d[3])
        : "r"(a[0]), "r"(a[1]), "r"(a[2]), "r"(a[3]), "r"(b0), "r"(b1));
}

// ---------------- fused kernel: proj+LN | codebook image | bias ----------------
__global__ void __launch_bounds__(P1_THREADS)
fused_prep_kernel(const float* __restrict__ x, const float* __restrict__ W,
                  const float* __restrict__ cb) {
    const int b = blockIdx.x;
    const int tid = threadIdx.x;

    __shared__ __align__(16) float xs[P1_TPB * P1_XS];   // 17408 B
    __shared__ __align__(16) float wt[P1_DC][CD];        // 4096 B

    if (b < NB_PROJ) {
        // ---- projection + LayerNorm: 64 tokens x 4 quarters, smem-staged ----
        const int t4  = tid & 3;
        const int row = tid >> 2;
        const int tokBase = b * P1_TPB;

        float acc[CD];
#pragma unroll
        for (int c = 0; c < CD; c++) acc[c] = 0.f;

        for (int dB = 0; dB < DIM; dB += P1_DC) {
            __syncthreads();
            // stage W chunk: coalesced LDG (consecutive d), transposed STS
#pragma unroll
            for (int i = 0; i < (P1_DC * CD) / P1_THREADS; i++) {
                int idx = tid + i * P1_THREADS;
                int c = idx >> 6, d = idx & 63;
                wt[d][c] = W[c * DIM + dB + d];
            }
            // stage x tile: 64 tokens x 64 floats, fully coalesced float4
#pragma unroll
            for (int i = 0; i < (P1_TPB * P1_DC / 4) / P1_THREADS; i++) {
                int idx = tid + i * P1_THREADS;     // 0..1023
                int tok = idx >> 4, q = idx & 15;
                float4 v = *reinterpret_cast<const float4*>(
                    x + (size_t)(tokBase + tok) * DIM + dB + q * 4);
                *reinterpret_cast<float4*>(xs + tok * P1_XS + q * 4) = v;
            }
            __syncthreads();

            const float* xr = xs + row * P1_XS + t4 * 16;
#pragma unroll
            for (int j = 0; j < 16; j++) {
                float xv = xr[j];
                const float4* w4 = reinterpret_cast<const float4*>(wt[t4 * 16 + j]);
                float4 w0 = w4[0], w1 = w4[1], w2 = w4[2], w3 = w4[3];
                acc[0]  = fmaf(xv, w0.x, acc[0]);
                acc[1]  = fmaf(xv, w0.y, acc[1]);
                acc[2]  = fmaf(xv, w0.z, acc[2]);
                acc[3]  = fmaf(xv, w0.w, acc[3]);
                acc[4]  = fmaf(xv, w1.x, acc[4]);
                acc[5]  = fmaf(xv, w1.y, acc[5]);
                acc[6]  = fmaf(xv, w1.z, acc[6]);
                acc[7]  = fmaf(xv, w1.w, acc[7]);
                acc[8]  = fmaf(xv, w2.x, acc[8]);
                acc[9]  = fmaf(xv, w2.y, acc[9]);
                acc[10] = fmaf(xv, w2.z, acc[10]);
                acc[11] = fmaf(xv, w2.w, acc[11]);
                acc[12] = fmaf(xv, w3.x, acc[12]);
                acc[13] = fmaf(xv, w3.y, acc[13]);
                acc[14] = fmaf(xv, w3.z, acc[14]);
                acc[15] = fmaf(xv, w3.w, acc[15]);
            }
        }

        // combine quarters within the quad
#pragma unroll
        for (int c = 0; c < CD; c++) {
            acc[c] += __shfl_xor_sync(0xffffffffu, acc[c], 1);
            acc[c] += __shfl_xor_sync(0xffffffffu, acc[c], 2);
        }
        if (t4 == 0) {
            float mu = 0.f;
#pragma unroll
            for (int c = 0; c < CD; c++) mu += acc[c];
            mu *= (1.0f / CD);
            float var = 0.f;
#pragma unroll
            for (int c = 0; c < CD; c++) { float d = acc[c] - mu; var = fmaf(d, d, var); }
            var *= (1.0f / CD);
            float inv = rsqrtf(var + 1e-5f);
            float* o = g_z + (size_t)(tokBase + row) * CD;
#pragma unroll
            for (int c = 0; c < CD; c++) o[c] = (acc[c] - mu) * inv;
        }
    } else if (b < NB_PROJ + NB_IMG) {
        // ---- split codebook -> B-fragment image ----
        int idx = (b - NB_PROJ) * 256 + tid;
        int k = idx >> 2;
        int t = idx & 3;
        const float* row = cb + (size_t)k * CD;
        float c0 = row[2 * t],     c1 = row[2 * t + 1];
        float c8 = row[2 * t + 8], c9 = row[2 * t + 9];
        unsigned short h0, m0, h1, m1, h8, m8, h9, m9;
        split2(c0, h0, m0); split2(c1, h1, m1);
        split2(c8, h8, m8); split2(c9, h9, m9);
        uint32_t wh0 = (uint32_t)h0 | ((uint32_t)h1 << 16);
        uint32_t wh1 = (uint32_t)h8 | ((uint32_t)h9 << 16);
        uint32_t wm0 = (uint32_t)m0 | ((uint32_t)m1 << 16);
        uint32_t wm1 = (uint32_t)m8 | ((uint32_t)m9 << 16);
        uint32_t* base = reinterpret_cast<uint32_t*>(g_img + (size_t)k * ROWB);
#pragma unroll
        for (int kb = 0; kb < KB; kb++) {
            uint32_t* p = base + kb * 8 + t * 2;
            if (lvlB(kb)) { p[0] = wm0; p[1] = wm1; }
            else          { p[0] = wh0; p[1] = wh1; }
        }
        if (t == 0) {
            uint4 zz = {0u, 0u, 0u, 0u};
            *reinterpret_cast<uint4*>(base + 24) = zz;
        }
    } else {
        // ---- -0.5*||c||^2 ----
        int k = (b - NB_PROJ - NB_IMG) * 256 + tid;
        float s = 0.f;
#pragma unroll
        for (int i = 0; i < CD; i++) {
            float v = cb[(size_t)k * CD + i];
            s = fmaf(v, v, s);
        }
        g_hbneg[k] = -0.5f * s;
    }
}

// ---------------- scan: warp-independent mma.sync + fused argmax ---------------
__global__ void __launch_bounds__(SCAN_THREADS)
scan_mma_kernel(float* __restrict__ out) {
    extern __shared__ __align__(16) unsigned char sm[];
    const uint32_t sb = smem_u32(sm);

    const int tid  = threadIdx.x;
    const int lane = tid & 31;
    const int w    = tid >> 5;
    const int g    = lane >> 2;
    const int t    = lane & 3;
    const int mi   = w >> 3;
    const int nj   = w & 7;
    const int m_base = mi * 64;
    const int njOff  = nj * WSLICE;
    const int ctaTok = blockIdx.x * 128;
    const uint32_t wbase = sb + w * WAREA;

    unsigned long long* res = reinterpret_cast<unsigned long long*>(sm + OFF_RES);
    if (tid < 128) res[tid] = 0ull;

    {
        const float4* src = reinterpret_cast<const float4*>(g_z + (size_t)ctaTok * CD);
        float4* dst = reinterpret_cast<float4*>(sm + OFF_Z);
        dst[tid] = src[tid];
    }
    __syncthreads();

    // ---- register-resident A fragments ----
    uint32_t afr[4][KB][4];
    {
        const float* zb = reinterpret_cast<const float*>(sm + OFF_Z);
        unsigned short sp[2][8][4];
#pragma unroll
        for (int s = 0; s < 8; s++) {
            int row = m_base + g + 8 * s;
#pragma unroll
            for (int jj = 0; jj < 4; jj++) {
                int col = 2 * t + ((jj & 2) ? 8 : 0) + (jj & 1);
                unsigned short h, m;
                split2(zb[row * CD + col], h, m);
                sp[0][s][jj] = h; sp[1][s][jj] = m;
            }
        }
#pragma unroll
        for (int mt = 0; mt < 4; mt++) {
#pragma unroll
            for (int kb = 0; kb < KB; kb++) {
                int lv = lvlA(kb);
                int s0 = 2 * mt, s1 = 2 * mt + 1;
                afr[mt][kb][0] = (uint32_t)sp[lv][s0][0] | ((uint32_t)sp[lv][s0][1] << 16);
                afr[mt][kb][1] = (uint32_t)sp[lv][s1][0] | ((uint32_t)sp[lv][s1][1] << 16);
                afr[mt][kb][2] = (uint32_t)sp[lv][s0][2] | ((uint32_t)sp[lv][s0][3] << 16);
                afr[mt][kb][3] = (uint32_t)sp[lv][s1][2] | ((uint32_t)sp[lv][s1][3] << 16);
            }
        }
    }

    // ---- per-warp staging ----
    auto stage = [&](int ch, int buf) {
        const unsigned char* src = g_img + (size_t)(ch * CHUNK_N + njOff) * ROWB;
        uint32_t dstB = wbase + buf * WSLICE_B;
        cpa16(dstB + lane * 16,        src + lane * 16);
        cpa16(dstB + (lane + 32) * 16, src + (lane + 32) * 16);
        cpa16(dstB + (lane + 64) * 16, src + (lane + 64) * 16);
        if (lane < 16) cpa16(dstB + (lane + 96) * 16, src + (lane + 96) * 16);
        if (lane < 4)
            cpa16(wbase + 2 * WSLICE_B + buf * 64 + lane * 16,
                  g_hbneg + ch * CHUNK_N + njOff + lane * 4);
        cpa_commit();
    };

    stage(0, 0);
    stage(1, 1);

    float best[8];
    int   bidx[8];
#pragma unroll
    for (int s = 0; s < 8; s++) { best[s] = -3.0e38f; bidx[s] = 0; }

    for (int ch = 0; ch < NCHUNK; ch++) {
        const int buf = ch & 1;
        if (ch < NCHUNK - 1) cpa_wait1(); else cpa_wait0();
        __syncwarp();

        const uint32_t bB = wbase + buf * WSLICE_B;
        const float* hbs = reinterpret_cast<const float*>(
            sm + (wbase - sb) + 2 * WSLICE_B + buf * 64);
        const int cbase = ch * CHUNK_N + njOff;

#pragma unroll
        for (int nt = 0; nt < 2; nt++) {
            const int lcol = nt * 8 + g;
            const float bx = hbs[nt * 8 + 2 * t];
            const float by = hbs[nt * 8 + 2 * t + 1];
            float d0[4], d1[4], d2[4], d3[4];
#pragma unroll
            for (int mt = 0; mt < 4; mt++) { d0[mt]=bx; d1[mt]=by; d2[mt]=bx; d3[mt]=by; }

#pragma unroll
            for (int kb = 0; kb < KB; kb++) {
                uint32_t b0, b1;
                uint32_t addr = bB + lcol * ROWB + kb * 32 + t * 8;
                asm volatile("ld.shared.v2.u32 {%0,%1}, [%2];"
                             : "=r"(b0), "=r"(b1) : "r"(addr));
#pragma unroll
                for (int mt = 0; mt < 4; mt++) {
                    float dd[4] = {d0[mt], d1[mt], d2[mt], d3[mt]};
                    mma16816(dd, afr[mt][kb], b0, b1);
                    d0[mt]=dd[0]; d1[mt]=dd[1]; d2[mt]=dd[2]; d3[mt]=dd[3];
                }
            }

            const int c0 = cbase + nt * 8 + 2 * t;
#pragma unroll
            for (int mt = 0; mt < 4; mt++) {
                int se = 2 * mt, so = 2 * mt + 1;
                {
                    float pm = fmaxf(d0[mt], d1[mt]);
                    float nb = fmaxf(best[se], pm);
                    if (nb != best[se])
                        bidx[se] = (d1[mt] > d0[mt]) ? c0 + 1 : c0;
                    best[se] = nb;
                }
                {
                    float pm = fmaxf(d2[mt], d3[mt]);
                    float nb = fmaxf(best[so], pm);
                    if (nb != best[so])
                        bidx[so] = (d3[mt] > d2[mt]) ? c0 + 1 : c0;
                    best[so] = nb;
                }
            }
        }

        if (ch + 2 < NCHUNK) stage(ch + 2, buf);
    }

    // ---- combine: quad shfl-reduce, then packed-key max across warps ----
#pragma unroll
    for (int s = 0; s < 8; s++) {
        unsigned int kh = ordf(best[s]);
        unsigned int kl = (unsigned int)(CS - 1 - bidx[s]);
#pragma unroll
        for (int o = 1; o < 4; o <<= 1) {
            unsigned int oh = __shfl_xor_sync(0xffffffffu, kh, o);
            unsigned int ol = __shfl_xor_sync(0xffffffffu, kl, o);
            if (oh > kh || (oh == kh && ol > kl)) { kh = oh; kl = ol; }
        }
        if (t == 0) {
            unsigned long long key = ((unsigned long long)kh << 32) | kl;
            atomicMax(&res[m_base + g + 8 * s], key);
        }
    }
    __syncthreads();

    if (tid < 128) {
        unsigned int low = (unsigned int)(res[tid] & 0xffffffffu);
        out[ctaTok + tid] = (float)(CS - 1 - (int)low);
    }
}

// ---------------- launch ----------------
extern "C" void kernel_launch(void* const* d_in, const int* in_sizes, int n_in,
                              void* d_out, int out_size) {
    const float* x  = nullptr;
    const float* W  = nullptr;
    const float* cb = nullptr;
    for (int i = 0; i < n_in; i++) {
        if      (in_sizes[i] == N_X)      x  = (const float*)d_in[i];
        else if (in_sizes[i] == N_W)      W  = (const float*)d_in[i];
        else if (in_sizes[i] == N_CB)     cb = (const float*)d_in[i];
        else if (in_sizes[i] == 4 * N_X)  x  = (const float*)d_in[i];
        else if (in_sizes[i] == 4 * N_W)  W  = (const float*)d_in[i];
        else if (in_sizes[i] == 4 * N_CB) cb = (const float*)d_in[i];
    }
    if (!x)  x  = (const float*)d_in[0];
    if (!W)  W  = (const float*)d_in[1];
    if (!cb) cb = (const float*)d_in[2];

    float* out = (float*)d_out;

    cudaFuncSetAttribute(scan_mma_kernel,
                         cudaFuncAttributeMaxDynamicSharedMemorySize, SCAN_SMEM);

    fused_prep_kernel<<<NB_FUSED, P1_THREADS>>>(x, W, cb);
    scan_mma_kernel<<<TOKENS / 128, SCAN_THREADS, SCAN_SMEM>>>(out);
}

// round 15
// speedup vs baseline: 1.0353x; 1.0353x over previous
#include <cuda_runtime.h>
#include <cuda_fp16.h>
#include <cstdint>

// Problem constants (fixed by setup_inputs)
#define TOKENS 16384
#define DIM    1024
#define CD     16
#define CS     8192

#define N_X  (TOKENS * DIM)
#define N_W  (CD * DIM)
#define N_CB (CS * CD)

// ---- scan tiling ----
#define CHUNK_N   128
#define NCHUNK    (CS / CHUNK_N)      // 64
#define ROWB      112                 // bytes/code row: 56 halves (48 data + 8 pad)
#define SCAN_THREADS 512
#define KB        3                   // fp16 2-split products: hh,hm,mh
#define WSLICE    16
#define WSLICE_B  (WSLICE * ROWB)     // 1792 B
#define WAREA     (2 * WSLICE_B + 2 * 64)

#define OFF_Z    (16 * WAREA)
#define OFF_RES  (OFF_Z + 128 * CD * 4)
#define SCAN_SMEM (OFF_RES + 128 * 8)

// proj config (fused kernel, R13 structure)
#define P1_THREADS 256
#define P1_TPB     64
#define P1_QS      4100
#define P1_SMEM    (4 * P1_QS * 4)    // 65600 B

#define NB_PROJ  (TOKENS / P1_TPB)          // 256
#define NB_IMG   (CS * 4 / 256)             // 128
#define NB_PREP  (CS / 256)                 // 32
#define NB_FUSED (NB_PROJ + NB_IMG + NB_PREP)

__device__ __align__(16) float g_z[TOKENS * CD];
__device__ float g_hbneg[CS];
__device__ __align__(16) unsigned char g_img[CS * ROWB];

// ---------------- helpers ----------------
__device__ __forceinline__ uint32_t smem_u32(const void* p) {
    uint32_t a;
    asm("{ .reg .u64 t; cvta.to.shared.u64 t, %1; cvt.u32.u64 %0, t; }"
        : "=r"(a) : "l"(p));
    return a;
}
__device__ __forceinline__ void cpa16(uint32_t dst, const void* src) {
    asm volatile("cp.async.ca.shared.global [%0], [%1], 16;"
                 :: "r"(dst), "l"(src) : "memory");
}
__device__ __forceinline__ void cpa_commit() {
    asm volatile("cp.async.commit_group;" ::: "memory");
}
__device__ __forceinline__ void cpa_wait1() {
    asm volatile("cp.async.wait_group 1;" ::: "memory");
}
__device__ __forceinline__ void cpa_wait0() {
    asm volatile("cp.async.wait_group 0;" ::: "memory");
}
__device__ __forceinline__ unsigned int ordf(float f) {
    unsigned int u = __float_as_uint(f);
    return (u & 0x80000000u) ? ~u : (u | 0x80000000u);
}
__device__ __forceinline__ void split2(float f, unsigned short& h, unsigned short& m) {
    __half hh = __float2half_rn(f);
    float fh = __half2float(hh);
    __half mm = __float2half_rn(f - fh);
    h = *reinterpret_cast<unsigned short*>(&hh);
    m = *reinterpret_cast<unsigned short*>(&mm);
}
__device__ __forceinline__ int lvlA(int kb) { return kb >> 1; }
__device__ __forceinline__ int lvlB(int kb) { return kb & 1; }

__device__ __forceinline__ void mma16816(float* d, const uint32_t* a,
                                         uint32_t b0, uint32_t b1) {
    asm volatile(
        "mma.sync.aligned.m16n8k16.row.col.f32.f16.f16.f32 "
        "{%0,%1,%2,%3},{%4,%5,%6,%7},{%8,%9},{%0,%1,%2,%3};"
        : "+f"(d[0]), "+f"(d[1]), "+f"(d[2]), "+f"(d[3])
        : "r"(a[0]), "r"(a[1]), "r"(a[2]), "r"(a[3]), "r"(b0), "r"(b1));
}

// ---------------- fused kernel: proj+LN | codebook image | bias ----------------
__global__ void __launch_bounds__(P1_THREADS)
fused_prep_kernel(const float* __restrict__ x, const float* __restrict__ W,
                  const float* __restrict__ cb) {
    const int b = blockIdx.x;
    const int tid = threadIdx.x;

    if (b < NB_PROJ) {
        // ---- projection + LayerNorm: 64 tokens x 4 d-interleaved lanes ----
        extern __shared__ __align__(16) float wt[];   // 4 * 4100 floats
        const int t4  = tid & 3;
        const int row = tid >> 2;
        const int token = b * P1_TPB + row;

        // stage W transposed (once per block): wt[dq*QS + dloc*16 + c]
        for (int i = 0; i < N_W / P1_THREADS; i++) {
            int idx = tid + i * P1_THREADS;
            int c = idx >> 10, d = idx & 1023;
            wt[(d >> 8) * P1_QS + (d & 255) * 16 + c] = W[idx];
        }
        __syncthreads();

        float acc[CD];
#pragma unroll
        for (int c = 0; c < CD; c++) acc[c] = 0.f;

        const float* xrow = x + (size_t)token * DIM;

        // lane t4 handles d = j*16 + t4*4 .. +3  (warp LDG covers 8 tokens x 64B
        // contiguous -> 8 lines/LDG instead of 32)
#pragma unroll 4
        for (int j = 0; j < 64; j++) {
            const int dbase = j * 16 + t4 * 4;
            float4 xv = *reinterpret_cast<const float4*>(xrow + dbase);
            const float* wr = wt + (dbase >> 8) * P1_QS + (dbase & 255) * 16;
#pragma unroll
            for (int e = 0; e < 4; e++) {
                float xe = (e == 0) ? xv.x : (e == 1) ? xv.y : (e == 2) ? xv.z : xv.w;
                const float4* w4 = reinterpret_cast<const float4*>(wr + e * 16);
                float4 p0 = w4[0], p1 = w4[1], p2 = w4[2], p3 = w4[3];
                acc[0]  = fmaf(xe, p0.x, acc[0]);
                acc[1]  = fmaf(xe, p0.y, acc[1]);
                acc[2]  = fmaf(xe, p0.z, acc[2]);
                acc[3]  = fmaf(xe, p0.w, acc[3]);
                acc[4]  = fmaf(xe, p1.x, acc[4]);
                acc[5]  = fmaf(xe, p1.y, acc[5]);
                acc[6]  = fmaf(xe, p1.z, acc[6]);
                acc[7]  = fmaf(xe, p1.w, acc[7]);
                acc[8]  = fmaf(xe, p2.x, acc[8]);
                acc[9]  = fmaf(xe, p2.y, acc[9]);
                acc[10] = fmaf(xe, p2.z, acc[10]);
                acc[11] = fmaf(xe, p2.w, acc[11]);
                acc[12] = fmaf(xe, p3.x, acc[12]);
                acc[13] = fmaf(xe, p3.y, acc[13]);
                acc[14] = fmaf(xe, p3.z, acc[14]);
                acc[15] = fmaf(xe, p3.w, acc[15]);
            }
        }

        // combine the 4 d-partitions within the quad
#pragma unroll
        for (int c = 0; c < CD; c++) {
            acc[c] += __shfl_xor_sync(0xffffffffu, acc[c], 1);
            acc[c] += __shfl_xor_sync(0xffffffffu, acc[c], 2);
        }
        if (t4 == 0) {
            float mu = 0.f;
#pragma unroll
            for (int c = 0; c < CD; c++) mu += acc[c];
            mu *= (1.0f / CD);
            float var = 0.f;
#pragma unroll
            for (int c = 0; c < CD; c++) { float d = acc[c] - mu; var = fmaf(d, d, var); }
            var *= (1.0f / CD);
            float inv = rsqrtf(var + 1e-5f);
            float* o = g_z + (size_t)token * CD;
#pragma unroll
            for (int c = 0; c < CD; c++) o[c] = (acc[c] - mu) * inv;
        }
    } else if (b < NB_PROJ + NB_IMG) {
        // ---- split codebook -> B-fragment image ----
        int idx = (b - NB_PROJ) * 256 + tid;
        int k = idx >> 2;
        int t = idx & 3;
        const float* row = cb + (size_t)k * CD;
        float c0 = row[2 * t],     c1 = row[2 * t + 1];
        float c8 = row[2 * t + 8], c9 = row[2 * t + 9];
        unsigned short h0, m0, h1, m1, h8, m8, h9, m9;
        split2(c0, h0, m0); split2(c1, h1, m1);
        split2(c8, h8, m8); split2(c9, h9, m9);
        uint32_t wh0 = (uint32_t)h0 | ((uint32_t)h1 << 16);
        uint32_t wh1 = (uint32_t)h8 | ((uint32_t)h9 << 16);
        uint32_t wm0 = (uint32_t)m0 | ((uint32_t)m1 << 16);
        uint32_t wm1 = (uint32_t)m8 | ((uint32_t)m9 << 16);
        uint32_t* base = reinterpret_cast<uint32_t*>(g_img + (size_t)k * ROWB);
#pragma unroll
        for (int kb = 0; kb < KB; kb++) {
            uint32_t* p = base + kb * 8 + t * 2;
            if (lvlB(kb)) { p[0] = wm0; p[1] = wm1; }
            else          { p[0] = wh0; p[1] = wh1; }
        }
        if (t == 0) {
            uint4 zz = {0u, 0u, 0u, 0u};
            *reinterpret_cast<uint4*>(base + 24) = zz;
        }
    } else {
        // ---- -0.5*||c||^2 ----
        int k = (b - NB_PROJ - NB_IMG) * 256 + tid;
        float s = 0.f;
#pragma unroll
        for (int i = 0; i < CD; i++) {
            float v = cb[(size_t)k * CD + i];
            s = fmaf(v, v, s);
        }
        g_hbneg[k] = -0.5f * s;
    }
}

// ---------------- scan: warp-independent mma.sync + fused argmax ---------------
__global__ void __launch_bounds__(SCAN_THREADS)
scan_mma_kernel(float* __restrict__ out) {
    extern __shared__ __align__(16) unsigned char sm[];
    const uint32_t sb = smem_u32(sm);

    const int tid  = threadIdx.x;
    const int lane = tid & 31;
    const int w    = tid >> 5;
    const int g    = lane >> 2;
    const int t    = lane & 3;
    const int mi   = w >> 3;
    const int nj   = w & 7;
    const int m_base = mi * 64;
    const int njOff  = nj * WSLICE;
    const int ctaTok = blockIdx.x * 128;
    const uint32_t wbase = sb + w * WAREA;

    unsigned long long* res = reinterpret_cast<unsigned long long*>(sm + OFF_RES);
    if (tid < 128) res[tid] = 0ull;

    {
        const float4* src = reinterpret_cast<const float4*>(g_z + (size_t)ctaTok * CD);
        float4* dst = reinterpret_cast<float4*>(sm + OFF_Z);
        dst[tid] = src[tid];
    }
    __syncthreads();

    // ---- register-resident A fragments ----
    uint32_t afr[4][KB][4];
    {
        const float* zb = reinterpret_cast<const float*>(sm + OFF_Z);
        unsigned short sp[2][8][4];
#pragma unroll
        for (int s = 0; s < 8; s++) {
            int row = m_base + g + 8 * s;
#pragma unroll
            for (int jj = 0; jj < 4; jj++) {
                int col = 2 * t + ((jj & 2) ? 8 : 0) + (jj & 1);
                unsigned short h, m;
                split2(zb[row * CD + col], h, m);
                sp[0][s][jj] = h; sp[1][s][jj] = m;
            }
        }
#pragma unroll
        for (int mt = 0; mt < 4; mt++) {
#pragma unroll
            for (int kb = 0; kb < KB; kb++) {
                int lv = lvlA(kb);
                int s0 = 2 * mt, s1 = 2 * mt + 1;
                afr[mt][kb][0] = (uint32_t)sp[lv][s0][0] | ((uint32_t)sp[lv][s0][1] << 16);
                afr[mt][kb][1] = (uint32_t)sp[lv][s1][0] | ((uint32_t)sp[lv][s1][1] << 16);
                afr[mt][kb][2] = (uint32_t)sp[lv][s0][2] | ((uint32_t)sp[lv][s0][3] << 16);
                afr[mt][kb][3] = (uint32_t)sp[lv][s1][2] | ((uint32_t)sp[lv][s1][3] << 16);
            }
        }
    }

    // ---- per-warp staging ----
    auto stage = [&](int ch, int buf) {
        const unsigned char* src = g_img + (size_t)(ch * CHUNK_N + njOff) * ROWB;
        uint32_t dstB = wbase + buf * WSLICE_B;
        cpa16(dstB + lane * 16,        src + lane * 16);
        cpa16(dstB + (lane + 32) * 16, src + (lane + 32) * 16);
        cpa16(dstB + (lane + 64) * 16, src + (lane + 64) * 16);
        if (lane < 16) cpa16(dstB + (lane + 96) * 16, src + (lane + 96) * 16);
        if (lane < 4)
            cpa16(wbase + 2 * WSLICE_B + buf * 64 + lane * 16,
                  g_hbneg + ch * CHUNK_N + njOff + lane * 4);
        cpa_commit();
    };

    stage(0, 0);
    stage(1, 1);

    float best[8];
    int   bidx[8];
#pragma unroll
    for (int s = 0; s < 8; s++) { best[s] = -3.0e38f; bidx[s] = 0; }

    for (int ch = 0; ch < NCHUNK; ch++) {
        const int buf = ch & 1;
        if (ch < NCHUNK - 1) cpa_wait1(); else cpa_wait0();
        __syncwarp();

        const uint32_t bB = wbase + buf * WSLICE_B;
        const float* hbs = reinterpret_cast<const float*>(
            sm + (wbase - sb) + 2 * WSLICE_B + buf * 64);
        const int cbase = ch * CHUNK_N + njOff;

#pragma unroll
        for (int nt = 0; nt < 2; nt++) {
            const int lcol = nt * 8 + g;
            const float bx = hbs[nt * 8 + 2 * t];
            const float by = hbs[nt * 8 + 2 * t + 1];
            float d0[4], d1[4], d2[4], d3[4];
#pragma unroll
            for (int mt = 0; mt < 4; mt++) { d0[mt]=bx; d1[mt]=by; d2[mt]=bx; d3[mt]=by; }

#pragma unroll
            for (int kb = 0; kb < KB; kb++) {
                uint32_t b0, b1;
                uint32_t addr = bB + lcol * ROWB + kb * 32 + t * 8;
                asm volatile("ld.shared.v2.u32 {%0,%1}, [%2];"
                             : "=r"(b0), "=r"(b1) : "r"(addr));
#pragma unroll
                for (int mt = 0; mt < 4; mt++) {
                    float dd[4] = {d0[mt], d1[mt], d2[mt], d3[mt]};
                    mma16816(dd, afr[mt][kb], b0, b1);
                    d0[mt]=dd[0]; d1[mt]=dd[1]; d2[mt]=dd[2]; d3[mt]=dd[3];
                }
            }

            const int c0 = cbase + nt * 8 + 2 * t;
#pragma unroll
            for (int mt = 0; mt < 4; mt++) {
                int se = 2 * mt, so = 2 * mt + 1;
                {
                    float pm = fmaxf(d0[mt], d1[mt]);
                    float nb = fmaxf(best[se], pm);
                    if (nb != best[se])
                        bidx[se] = (d1[mt] > d0[mt]) ? c0 + 1 : c0;
                    best[se] = nb;
                }
                {
                    float pm = fmaxf(d2[mt], d3[mt]);
                    float nb = fmaxf(best[so], pm);
                    if (nb != best[so])
                        bidx[so] = (d3[mt] > d2[mt]) ? c0 + 1 : c0;
                    best[so] = nb;
                }
            }
        }

        if (ch + 2 < NCHUNK) stage(ch + 2, buf);
    }

    // ---- combine: quad shfl-reduce, then packed-key max across warps ----
#pragma unroll
    for (int s = 0; s < 8; s++) {
        unsigned int kh = ordf(best[s]);
        unsigned int kl = (unsigned int)(CS - 1 - bidx[s]);
#pragma unroll
        for (int o = 1; o < 4; o <<= 1) {
            unsigned int oh = __shfl_xor_sync(0xffffffffu, kh, o);
            unsigned int ol = __shfl_xor_sync(0xffffffffu, kl, o);
            if (oh > kh || (oh == kh && ol > kl)) { kh = oh; kl = ol; }
        }
        if (t == 0) {
            unsigned long long key = ((unsigned long long)kh << 32) | kl;
            atomicMax(&res[m_base + g + 8 * s], key);
        }
    }
    __syncthreads();

    if (tid < 128) {
        unsigned int low = (unsigned int)(res[tid] & 0xffffffffu);
        out[ctaTok + tid] = (float)(CS - 1 - (int)low);
    }
}

// ---------------- launch ----------------
extern "C" void kernel_launch(void* const* d_in, const int* in_sizes, int n_in,
                              void* d_out, int out_size) {
    const float* x  = nullptr;
    const float* W  = nullptr;
    const float* cb = nullptr;
    for (int i = 0; i < n_in; i++) {
        if      (in_sizes[i] == N_X)      x  = (const float*)d_in[i];
        else if (in_sizes[i] == N_W)      W  = (const float*)d_in[i];
        else if (in_sizes[i] == N_CB)     cb = (const float*)d_in[i];
        else if (in_sizes[i] == 4 * N_X)  x  = (const float*)d_in[i];
        else if (in_sizes[i] == 4 * N_W)  W  = (const float*)d_in[i];
        else if (in_sizes[i] == 4 * N_CB) cb = (const float*)d_in[i];
    }
    if (!x)  x  = (const float*)d_in[0];
    if (!W)  W  = (const float*)d_in[1];
    if (!cb) cb = (const float*)d_in[2];

    float* out = (float*)d_out;

    cudaFuncSetAttribute(scan_mma_kernel,
                         cudaFuncAttributeMaxDynamicSharedMemorySize, SCAN_SMEM);
    cudaFuncSetAttribute(fused_prep_kernel,
                         cudaFuncAttributeMaxDynamicSharedMemorySize, P1_SMEM);

    fused_prep_kernel<<<NB_FUSED, P1_THREADS, P1_SMEM>>>(x, W, cb);
    scan_mma_kernel<<<TOKENS / 128, SCAN_THREADS, SCAN_SMEM>>>(out);
}

// round 16
// speedup vs baseline: 2.2109x; 2.1356x over previous
#include <cuda_runtime.h>
#include <cuda_fp16.h>
#include <cstdint>

// Problem constants (fixed by setup_inputs)
#define TOKENS 16384
#define DIM    1024
#define CD     16
#define CS     8192

#define N_X  (TOKENS * DIM)
#define N_W  (CD * DIM)
#define N_CB (CS * CD)

// ---- scan tiling ----
#define CHUNK_N   128
#define NCHUNK    (CS / CHUNK_N)      // 64
#define ROWB      112                 // bytes/code row: 56 halves (48 data + 8 pad)
#define SCAN_THREADS 512
#define KB        3                   // fp16 2-split products: hh,hm,mh
#define WSLICE    16
#define WSLICE_B  (WSLICE * ROWB)     // 1792 B
#define WAREA     (2 * WSLICE_B + 2 * 64)

#define OFF_Z    (16 * WAREA)
#define OFF_RES  (OFF_Z + 128 * CD * 4)
#define SCAN_SMEM (OFF_RES + 128 * 8)

// proj config (R13 structure, 2 tokens/thread)
#define P1_THREADS 256
#define P1_TPB     128                // tokens per block (4 thr/token, 2 tokens each)
#define P1_QS      4100
#define P1_SMEM    (4 * P1_QS * 4)    // 65600 B

#define NB_PROJ  (TOKENS / P1_TPB)          // 128
#define NB_IMG   (CS * 4 / 256)             // 128
#define NB_PREP  (CS / 256)                 // 32
#define NB_FUSED (NB_PROJ + NB_IMG + NB_PREP)

__device__ __align__(16) float g_z[TOKENS * CD];
__device__ float g_hbneg[CS];
__device__ __align__(16) unsigned char g_img[CS * ROWB];

// ---------------- helpers ----------------
__device__ __forceinline__ uint32_t smem_u32(const void* p) {
    uint32_t a;
    asm("{ .reg .u64 t; cvta.to.shared.u64 t, %1; cvt.u32.u64 %0, t; }"
        : "=r"(a) : "l"(p));
    return a;
}
__device__ __forceinline__ void cpa16(uint32_t dst, const void* src) {
    asm volatile("cp.async.ca.shared.global [%0], [%1], 16;"
                 :: "r"(dst), "l"(src) : "memory");
}
__device__ __forceinline__ void cpa_commit() {
    asm volatile("cp.async.commit_group;" ::: "memory");
}
__device__ __forceinline__ void cpa_wait1() {
    asm volatile("cp.async.wait_group 1;" ::: "memory");
}
__device__ __forceinline__ void cpa_wait0() {
    asm volatile("cp.async.wait_group 0;" ::: "memory");
}
__device__ __forceinline__ unsigned int ordf(float f) {
    unsigned int u = __float_as_uint(f);
    return (u & 0x80000000u) ? ~u : (u | 0x80000000u);
}
__device__ __forceinline__ void split2(float f, unsigned short& h, unsigned short& m) {
    __half hh = __float2half_rn(f);
    float fh = __half2float(hh);
    __half mm = __float2half_rn(f - fh);
    h = *reinterpret_cast<unsigned short*>(&hh);
    m = *reinterpret_cast<unsigned short*>(&mm);
}
__device__ __forceinline__ int lvlA(int kb) { return kb >> 1; }
__device__ __forceinline__ int lvlB(int kb) { return kb & 1; }

__device__ __forceinline__ void mma16816(float* d, const uint32_t* a,
                                         uint32_t b0, uint32_t b1) {
    asm volatile(
        "mma.sync.aligned.m16n8k16.row.col.f32.f16.f16.f32 "
        "{%0,%1,%2,%3},{%4,%5,%6,%7},{%8,%9},{%0,%1,%2,%3};"
        : "+f"(d[0]), "+f"(d[1]), "+f"(d[2]), "+f"(d[3])
        : "r"(a[0]), "r"(a[1]), "r"(a[2]), "r"(a[3]), "r"(b0), "r"(b1));
}

// ---------------- fused kernel: proj+LN | codebook image | bias ----------------
__global__ void __launch_bounds__(P1_THREADS)
fused_prep_kernel(const float* __restrict__ x, const float* __restrict__ W,
                  const float* __restrict__ cb) {
    const int b = blockIdx.x;
    const int tid = threadIdx.x;

    if (b < NB_PROJ) {
        // ---- projection + LayerNorm: 128 tokens, 4 thr/token, 2 tokens/thread ----
        // x access per token: own contiguous quarter (R13 pattern, proven fast).
        extern __shared__ __align__(16) float wt[];   // 4 * 4100 floats
        const int t4  = tid & 3;
        const int row = tid >> 2;                     // 0..63
        const int tok0 = b * P1_TPB + row;
        const int tok1 = tok0 + 64;

        // stage W transposed (once per block): wt[dq*QS + dloc*16 + c]
        for (int i = 0; i < N_W / P1_THREADS; i++) {
            int idx = tid + i * P1_THREADS;
            int c = idx >> 10, d = idx & 1023;
            wt[(d >> 8) * P1_QS + (d & 255) * 16 + c] = W[idx];
        }
        __syncthreads();

        float a0[CD], a1[CD];
#pragma unroll
        for (int c = 0; c < CD; c++) { a0[c] = 0.f; a1[c] = 0.f; }

        const float* xr0 = x + (size_t)tok0 * DIM + t4 * 256;
        const float* xr1 = x + (size_t)tok1 * DIM + t4 * 256;
        const float* wq = wt + t4 * P1_QS;

        for (int db = 0; db < 256; db += 4) {
            float4 xv0 = *reinterpret_cast<const float4*>(xr0 + db);
            float4 xv1 = *reinterpret_cast<const float4*>(xr1 + db);
            const float* w0 = wq + (db + 0) * 16;
            const float* w1 = wq + (db + 1) * 16;
            const float* w2 = wq + (db + 2) * 16;
            const float* w3 = wq + (db + 3) * 16;
#pragma unroll
            for (int c = 0; c < CD; c++) {
                float wv0 = w0[c], wv1 = w1[c], wv2 = w2[c], wv3 = w3[c];
                a0[c] = fmaf(xv0.x, wv0, a0[c]);
                a0[c] = fmaf(xv0.y, wv1, a0[c]);
                a0[c] = fmaf(xv0.z, wv2, a0[c]);
                a0[c] = fmaf(xv0.w, wv3, a0[c]);
                a1[c] = fmaf(xv1.x, wv0, a1[c]);
                a1[c] = fmaf(xv1.y, wv1, a1[c]);
                a1[c] = fmaf(xv1.z, wv2, a1[c]);
                a1[c] = fmaf(xv1.w, wv3, a1[c]);
            }
        }

        // combine 4 quarters within the quad
#pragma unroll
        for (int c = 0; c < CD; c++) {
            a0[c] += __shfl_xor_sync(0xffffffffu, a0[c], 1);
            a0[c] += __shfl_xor_sync(0xffffffffu, a0[c], 2);
            a1[c] += __shfl_xor_sync(0xffffffffu, a1[c], 1);
            a1[c] += __shfl_xor_sync(0xffffffffu, a1[c], 2);
        }
        if (t4 == 0) {
            {
                float mu = 0.f;
#pragma unroll
                for (int c = 0; c < CD; c++) mu += a0[c];
                mu *= (1.0f / CD);
                float var = 0.f;
#pragma unroll
                for (int c = 0; c < CD; c++) { float d = a0[c] - mu; var = fmaf(d, d, var); }
                var *= (1.0f / CD);
                float inv = rsqrtf(var + 1e-5f);
                float* o = g_z + (size_t)tok0 * CD;
#pragma unroll
                for (int c = 0; c < CD; c++) o[c] = (a0[c] - mu) * inv;
            }
            {
                float mu = 0.f;
#pragma unroll
                for (int c = 0; c < CD; c++) mu += a1[c];
                mu *= (1.0f / CD);
                float var = 0.f;
#pragma unroll
                for (int c = 0; c < CD; c++) { float d = a1[c] - mu; var = fmaf(d, d, var); }
                var *= (1.0f / CD);
                float inv = rsqrtf(var + 1e-5f);
                float* o = g_z + (size_t)tok1 * CD;
#pragma unroll
                for (int c = 0; c < CD; c++) o[c] = (a1[c] - mu) * inv;
            }
        }
    } else if (b < NB_PROJ + NB_IMG) {
        // ---- split codebook -> B-fragment image ----
        int idx = (b - NB_PROJ) * 256 + tid;
        int k = idx >> 2;
        int t = idx & 3;
        const float* row = cb + (size_t)k * CD;
        float c0 = row[2 * t],     c1 = row[2 * t + 1];
        float c8 = row[2 * t + 8], c9 = row[2 * t + 9];
        unsigned short h0, m0, h1, m1, h8, m8, h9, m9;
        split2(c0, h0, m0); split2(c1, h1, m1);
        split2(c8, h8, m8); split2(c9, h9, m9);
        uint32_t wh0 = (uint32_t)h0 | ((uint32_t)h1 << 16);
        uint32_t wh1 = (uint32_t)h8 | ((uint32_t)h9 << 16);
        uint32_t wm0 = (uint32_t)m0 | ((uint32_t)m1 << 16);
        uint32_t wm1 = (uint32_t)m8 | ((uint32_t)m9 << 16);
        uint32_t* base = reinterpret_cast<uint32_t*>(g_img + (size_t)k * ROWB);
#pragma unroll
        for (int kb = 0; kb < KB; kb++) {
            uint32_t* p = base + kb * 8 + t * 2;
            if (lvlB(kb)) { p[0] = wm0; p[1] = wm1; }
            else          { p[0] = wh0; p[1] = wh1; }
        }
        if (t == 0) {
            uint4 zz = {0u, 0u, 0u, 0u};
            *reinterpret_cast<uint4*>(base + 24) = zz;
        }
    } else {
        // ---- -0.5*||c||^2 ----
        int k = (b - NB_PROJ - NB_IMG) * 256 + tid;
        float s = 0.f;
#pragma unroll
        for (int i = 0; i < CD; i++) {
            float v = cb[(size_t)k * CD + i];
            s = fmaf(v, v, s);
        }
        g_hbneg[k] = -0.5f * s;
    }
}

// ---------------- scan: warp-independent mma.sync + fused argmax ---------------
__global__ void __launch_bounds__(SCAN_THREADS)
scan_mma_kernel(float* __restrict__ out) {
    extern __shared__ __align__(16) unsigned char sm[];
    const uint32_t sb = smem_u32(sm);

    const int tid  = threadIdx.x;
    const int lane = tid & 31;
    const int w    = tid >> 5;
    const int g    = lane >> 2;
    const int t    = lane & 3;
    const int mi   = w >> 3;
    const int nj   = w & 7;
    const int m_base = mi * 64;
    const int njOff  = nj * WSLICE;
    const int ctaTok = blockIdx.x * 128;
    const uint32_t wbase = sb + w * WAREA;

    unsigned long long* res = reinterpret_cast<unsigned long long*>(sm + OFF_RES);
    if (tid < 128) res[tid] = 0ull;

    {
        const float4* src = reinterpret_cast<const float4*>(g_z + (size_t)ctaTok * CD);
        float4* dst = reinterpret_cast<float4*>(sm + OFF_Z);
        dst[tid] = src[tid];
    }
    __syncthreads();

    // ---- register-resident A fragments ----
    uint32_t afr[4][KB][4];
    {
        const float* zb = reinterpret_cast<const float*>(sm + OFF_Z);
        unsigned short sp[2][8][4];
#pragma unroll
        for (int s = 0; s < 8; s++) {
            int row = m_base + g + 8 * s;
#pragma unroll
            for (int jj = 0; jj < 4; jj++) {
                int col = 2 * t + ((jj & 2) ? 8 : 0) + (jj & 1);
                unsigned short h, m;
                split2(zb[row * CD + col], h, m);
                sp[0][s][jj] = h; sp[1][s][jj] = m;
            }
        }
#pragma unroll
        for (int mt = 0; mt < 4; mt++) {
#pragma unroll
            for (int kb = 0; kb < KB; kb++) {
                int lv = lvlA(kb);
                int s0 = 2 * mt, s1 = 2 * mt + 1;
                afr[mt][kb][0] = (uint32_t)sp[lv][s0][0] | ((uint32_t)sp[lv][s0][1] << 16);
                afr[mt][kb][1] = (uint32_t)sp[lv][s1][0] | ((uint32_t)sp[lv][s1][1] << 16);
                afr[mt][kb][2] = (uint32_t)sp[lv][s0][2] | ((uint32_t)sp[lv][s0][3] << 16);
                afr[mt][kb][3] = (uint32_t)sp[lv][s1][2] | ((uint32_t)sp[lv][s1][3] << 16);
            }
        }
    }

    // ---- per-warp staging ----
    auto stage = [&](int ch, int buf) {
        const unsigned char* src = g_img + (size_t)(ch * CHUNK_N + njOff) * ROWB;
        uint32_t dstB = wbase + buf * WSLICE_B;
        cpa16(dstB + lane * 16,        src + lane * 16);
        cpa16(dstB + (lane + 32) * 16, src + (lane + 32) * 16);
        cpa16(dstB + (lane + 64) * 16, src + (lane + 64) * 16);
        if (lane < 16) cpa16(dstB + (lane + 96) * 16, src + (lane + 96) * 16);
        if (lane < 4)
            cpa16(wbase + 2 * WSLICE_B + buf * 64 + lane * 16,
                  g_hbneg + ch * CHUNK_N + njOff + lane * 4);
        cpa_commit();
    };

    stage(0, 0);
    stage(1, 1);

    float best[8];
    int   bidx[8];
#pragma unroll
    for (int s = 0; s < 8; s++) { best[s] = -3.0e38f; bidx[s] = 0; }

    for (int ch = 0; ch < NCHUNK; ch++) {
        const int buf = ch & 1;
        if (ch < NCHUNK - 1) cpa_wait1(); else cpa_wait0();
        __syncwarp();

        const uint32_t bB = wbase + buf * WSLICE_B;
        const float* hbs = reinterpret_cast<const float*>(
            sm + (wbase - sb) + 2 * WSLICE_B + buf * 64);
        const int cbase = ch * CHUNK_N + njOff;

#pragma unroll
        for (int nt = 0; nt < 2; nt++) {
            const int lcol = nt * 8 + g;
            const float bx = hbs[nt * 8 + 2 * t];
            const float by = hbs[nt * 8 + 2 * t + 1];
            float d0[4], d1[4], d2[4], d3[4];
#pragma unroll
            for (int mt = 0; mt < 4; mt++) { d0[mt]=bx; d1[mt]=by; d2[mt]=bx; d3[mt]=by; }

#pragma unroll
            for (int kb = 0; kb < KB; kb++) {
                uint32_t b0, b1;
                uint32_t addr = bB + lcol * ROWB + kb * 32 + t * 8;
                asm volatile("ld.shared.v2.u32 {%0,%1}, [%2];"
                             : "=r"(b0), "=r"(b1) : "r"(addr));
#pragma unroll
                for (int mt = 0; mt < 4; mt++) {
                    float dd[4] = {d0[mt], d1[mt], d2[mt], d3[mt]};
                    mma16816(dd, afr[mt][kb], b0, b1);
                    d0[mt]=dd[0]; d1[mt]=dd[1]; d2[mt]=dd[2]; d3[mt]=dd[3];
                }
            }

            const int c0 = cbase + nt * 8 + 2 * t;
#pragma unroll
            for (int mt = 0; mt < 4; mt++) {
                int se = 2 * mt, so = 2 * mt + 1;
                {
                    float pm = fmaxf(d0[mt], d1[mt]);
                    float nb = fmaxf(best[se], pm);
                    if (nb != best[se])
                        bidx[se] = (d1[mt] > d0[mt]) ? c0 + 1 : c0;
                    best[se] = nb;
                }
                {
                    float pm = fmaxf(d2[mt], d3[mt]);
                    float nb = fmaxf(best[so], pm);
                    if (nb != best[so])
                        bidx[so] = (d3[mt] > d2[mt]) ? c0 + 1 : c0;
                    best[so] = nb;
                }
            }
        }

        if (ch + 2 < NCHUNK) stage(ch + 2, buf);
    }

    // ---- combine: quad shfl-reduce, then packed-key max across warps ----
#pragma unroll
    for (int s = 0; s < 8; s++) {
        unsigned int kh = ordf(best[s]);
        unsigned int kl = (unsigned int)(CS - 1 - bidx[s]);
#pragma unroll
        for (int o = 1; o < 4; o <<= 1) {
            unsigned int oh = __shfl_xor_sync(0xffffffffu, kh, o);
            unsigned int ol = __shfl_xor_sync(0xffffffffu, kl, o);
            if (oh > kh || (oh == kh && ol > kl)) { kh = oh; kl = ol; }
        }
        if (t == 0) {
            unsigned long long key = ((unsigned long long)kh << 32) | kl;
            atomicMax(&res[m_base + g + 8 * s], key);
        }
    }
    __syncthreads();

    if (tid < 128) {
        unsigned int low = (unsigned int)(res[tid] & 0xffffffffu);
        out[ctaTok + tid] = (float)(CS - 1 - (int)low);
    }
}

// ---------------- launch ----------------
extern "C" void kernel_launch(void* const* d_in, const int* in_sizes, int n_in,
                              void* d_out, int out_size) {
    const float* x  = nullptr;
    const float* W  = nullptr;
    const float* cb = nullptr;
    for (int i = 0; i < n_in; i++) {
        if      (in_sizes[i] == N_X)      x  = (const float*)d_in[i];
        else if (in_sizes[i] == N_W)      W  = (const float*)d_in[i];
        else if (in_sizes[i] == N_CB)     cb = (const float*)d_in[i];
        else if (in_sizes[i] == 4 * N_X)  x  = (const float*)d_in[i];
        else if (in_sizes[i] == 4 * N_W)  W  = (const float*)d_in[i];
        else if (in_sizes[i] == 4 * N_CB) cb = (const float*)d_in[i];
    }
    if (!x)  x  = (const float*)d_in[0];
    if (!W)  W  = (const float*)d_in[1];
    if (!cb) cb = (const float*)d_in[2];

    float* out = (float*)d_out;

    cudaFuncSetAttribute(scan_mma_kernel,
                         cudaFuncAttributeMaxDynamicSharedMemorySize, SCAN_SMEM);
    cudaFuncSetAttribute(fused_prep_kernel,
                         cudaFuncAttributeMaxDynamicSharedMemorySize, P1_SMEM);

    fused_prep_kernel<<<NB_FUSED, P1_THREADS, P1_SMEM>>>(x, W, cb);
    scan_mma_kernel<<<TOKENS / 128, SCAN_THREADS, SCAN_SMEM>>>(out);
}